// round 1
// baseline (speedup 1.0000x reference)
#include <cuda_runtime.h>
#include <cuda_bf16.h>

#define BATCH 16
#define CCH   512
#define NPIX  4096

// Scratch: energy / attention matrices, 16*512*512 fp32 = 16 MB
__device__ float g_energy[(size_t)BATCH * CCH * CCH];

// ---------------------------------------------------------------------------
// Kernel 1: energy[b] = q[b] @ q[b]^T   (q = x reshaped [C, N], NT GEMM)
// Tile 128x128x16, 256 threads, 8x8 per thread.
// ---------------------------------------------------------------------------
__global__ __launch_bounds__(256) void energy_kernel(const float* __restrict__ x)
{
    constexpr int BM = 128, BN = 128, BK = 16;
    __shared__ float As[BK][BM + 4];
    __shared__ float Bs[BK][BN + 4];

    const int b  = blockIdx.z;
    const float* q = x + (size_t)b * CCH * NPIX;
    float* E = g_energy + (size_t)b * CCH * CCH;

    const int m0 = blockIdx.y * BM;
    const int n0 = blockIdx.x * BN;
    const int tid = threadIdx.x;
    const int tx = tid & 15;        // output col group
    const int ty = tid >> 4;        // output row group
    const int lrow = tid >> 2;      // 0..63  (load row)
    const int lq   = tid & 3;       // float4 quad within 16-wide k slab

    float acc[8][8];
#pragma unroll
    for (int i = 0; i < 8; i++)
#pragma unroll
        for (int j = 0; j < 8; j++) acc[i][j] = 0.f;

    for (int k0 = 0; k0 < NPIX; k0 += BK) {
#pragma unroll
        for (int h = 0; h < 2; h++) {
            const int r = lrow + h * 64;
            float4 va = *(const float4*)(q + (size_t)(m0 + r) * NPIX + k0 + lq * 4);
            As[lq * 4 + 0][r] = va.x; As[lq * 4 + 1][r] = va.y;
            As[lq * 4 + 2][r] = va.z; As[lq * 4 + 3][r] = va.w;
            float4 vb = *(const float4*)(q + (size_t)(n0 + r) * NPIX + k0 + lq * 4);
            Bs[lq * 4 + 0][r] = vb.x; Bs[lq * 4 + 1][r] = vb.y;
            Bs[lq * 4 + 2][r] = vb.z; Bs[lq * 4 + 3][r] = vb.w;
        }
        __syncthreads();
#pragma unroll
        for (int k = 0; k < BK; k++) {
            float a[8], bv[8];
#pragma unroll
            for (int i = 0; i < 8; i++) a[i]  = As[k][ty * 8 + i];
#pragma unroll
            for (int j = 0; j < 8; j++) bv[j] = Bs[k][tx * 8 + j];
#pragma unroll
            for (int i = 0; i < 8; i++)
#pragma unroll
                for (int j = 0; j < 8; j++)
                    acc[i][j] = fmaf(a[i], bv[j], acc[i][j]);
        }
        __syncthreads();
    }

#pragma unroll
    for (int i = 0; i < 8; i++) {
        float* dst = E + (size_t)(m0 + ty * 8 + i) * CCH + n0 + tx * 8;
        *(float4*)(dst + 0) = make_float4(acc[i][0], acc[i][1], acc[i][2], acc[i][3]);
        *(float4*)(dst + 4) = make_float4(acc[i][4], acc[i][5], acc[i][6], acc[i][7]);
    }
}

// ---------------------------------------------------------------------------
// Kernel 2: in-place row softmax of (rowmax - e)  ==  exp(rowmin - e)/sum
// One warp per row of 512.
// ---------------------------------------------------------------------------
__global__ __launch_bounds__(256) void softmax_kernel()
{
    const int row  = blockIdx.x * 8 + (threadIdx.x >> 5);
    const int lane = threadIdx.x & 31;
    float* e = g_energy + (size_t)row * CCH;

    float v[16];
    float mn = 3.4e38f;
#pragma unroll
    for (int i = 0; i < 16; i++) {
        v[i] = e[lane + i * 32];
        mn = fminf(mn, v[i]);
    }
#pragma unroll
    for (int o = 16; o > 0; o >>= 1)
        mn = fminf(mn, __shfl_xor_sync(0xffffffffu, mn, o));

    float s = 0.f;
#pragma unroll
    for (int i = 0; i < 16; i++) {
        v[i] = expf(mn - v[i]);
        s += v[i];
    }
#pragma unroll
    for (int o = 16; o > 0; o >>= 1)
        s += __shfl_xor_sync(0xffffffffu, s, o);

    const float r = 1.0f / s;
#pragma unroll
    for (int i = 0; i < 16; i++)
        e[lane + i * 32] = v[i] * r;
}

// ---------------------------------------------------------------------------
// Kernel 3: y[b] = gamma * (attn[b] @ q[b]) + x[b]   (NN GEMM, M=512 N=4096 K=512)
// ---------------------------------------------------------------------------
__global__ __launch_bounds__(256) void out_kernel(const float* __restrict__ x,
                                                  const float* __restrict__ gamma,
                                                  float* __restrict__ out)
{
    constexpr int BM = 128, BN = 128, BK = 16;
    __shared__ float As[BK][BM + 4];
    __shared__ float Bs[BK][BN + 4];

    const int b = blockIdx.z;
    const float* A = g_energy + (size_t)b * CCH * CCH;   // attention
    const float* q = x + (size_t)b * CCH * NPIX;

    const int m0 = blockIdx.y * BM;
    const int n0 = blockIdx.x * BN;
    const int tid = threadIdx.x;
    const int tx = tid & 15;
    const int ty = tid >> 4;
    const int lrow = tid >> 2;      // A-tile: 0..63
    const int lq   = tid & 3;
    const int brow = tid >> 5;      // B-tile: 0..7
    const int bcol = tid & 31;

    float acc[8][8];
#pragma unroll
    for (int i = 0; i < 8; i++)
#pragma unroll
        for (int j = 0; j < 8; j++) acc[i][j] = 0.f;

    for (int k0 = 0; k0 < CCH; k0 += BK) {
#pragma unroll
        for (int h = 0; h < 2; h++) {
            const int r = lrow + h * 64;
            float4 va = *(const float4*)(A + (size_t)(m0 + r) * CCH + k0 + lq * 4);
            As[lq * 4 + 0][r] = va.x; As[lq * 4 + 1][r] = va.y;
            As[lq * 4 + 2][r] = va.z; As[lq * 4 + 3][r] = va.w;
        }
#pragma unroll
        for (int h = 0; h < 2; h++) {
            const int r = brow + h * 8;
            float4 vb = *(const float4*)(q + (size_t)(k0 + r) * NPIX + n0 + bcol * 4);
            *(float4*)&Bs[r][bcol * 4] = vb;
        }
        __syncthreads();
#pragma unroll
        for (int k = 0; k < BK; k++) {
            float a[8], bv[8];
#pragma unroll
            for (int i = 0; i < 8; i++) a[i]  = As[k][ty * 8 + i];
#pragma unroll
            for (int j = 0; j < 8; j++) bv[j] = Bs[k][tx * 8 + j];
#pragma unroll
            for (int i = 0; i < 8; i++)
#pragma unroll
                for (int j = 0; j < 8; j++)
                    acc[i][j] = fmaf(a[i], bv[j], acc[i][j]);
        }
        __syncthreads();
    }

    const float g = *gamma;
#pragma unroll
    for (int i = 0; i < 8; i++) {
        const int m = m0 + ty * 8 + i;
        const size_t base = (size_t)(b * CCH + m) * NPIX + n0 + tx * 8;
        float4 x0 = *(const float4*)(x + base);
        float4 x1 = *(const float4*)(x + base + 4);
        float4 o0, o1;
        o0.x = fmaf(g, acc[i][0], x0.x); o0.y = fmaf(g, acc[i][1], x0.y);
        o0.z = fmaf(g, acc[i][2], x0.z); o0.w = fmaf(g, acc[i][3], x0.w);
        o1.x = fmaf(g, acc[i][4], x1.x); o1.y = fmaf(g, acc[i][5], x1.y);
        o1.z = fmaf(g, acc[i][6], x1.z); o1.w = fmaf(g, acc[i][7], x1.w);
        *(float4*)(out + base)     = o0;
        *(float4*)(out + base + 4) = o1;
    }
}

// ---------------------------------------------------------------------------
extern "C" void kernel_launch(void* const* d_in, const int* in_sizes, int n_in,
                              void* d_out, int out_size)
{
    const float* x     = (const float*)d_in[0];
    const float* gamma = (const float*)d_in[1];
    float* out = (float*)d_out;

    // energy = q q^T : grid (C/128, C/128, B)
    energy_kernel<<<dim3(CCH / 128, CCH / 128, BATCH), 256>>>(x);
    // softmax: 8 warps (rows) per 256-thread block
    softmax_kernel<<<(BATCH * CCH) / 8, 256>>>();
    // out = gamma * attn @ q + x : grid (N/128, C/128, B)
    out_kernel<<<dim3(NPIX / 128, CCH / 128, BATCH), 256>>>(x, gamma, out);
}

// round 3
// speedup vs baseline: 1.5448x; 1.5448x over previous
#include <cuda_runtime.h>
#include <cstdint>

#define BATCH 16
#define CCH   512
#define NPIX  4096

// attention / energy scratch: 16 MB
__device__ float g_energy[(size_t)BATCH * CCH * CCH];

// ---------------------------------------------------------------------------
// helpers
// ---------------------------------------------------------------------------
__device__ __forceinline__ uint32_t hi_tf32(float x) {
    return __float_as_uint(x) & 0xFFFFE000u;   // exact tf32 (top 19 bits)
}
__device__ __forceinline__ uint32_t lo_tf32(float x, uint32_t hibits) {
    float lo = x - __uint_as_float(hibits);
    uint32_t r;
    asm("cvt.rna.tf32.f32 %0, %1;" : "=r"(r) : "f"(lo));
    return r;
}
__device__ __forceinline__ void mma8(float* d, const uint32_t* a, const uint32_t* b) {
    asm volatile(
        "mma.sync.aligned.m16n8k8.row.col.f32.tf32.tf32.f32 "
        "{%0,%1,%2,%3}, {%4,%5,%6,%7}, {%8,%9}, {%0,%1,%2,%3};"
        : "+f"(d[0]), "+f"(d[1]), "+f"(d[2]), "+f"(d[3])
        : "r"(a[0]), "r"(a[1]), "r"(a[2]), "r"(a[3]), "r"(b[0]), "r"(b[1]));
}
__device__ __forceinline__ void split_store(uint32_t* dH, uint32_t* dL, float4 v) {
    uint4 h, l;
    h.x = hi_tf32(v.x); h.y = hi_tf32(v.y); h.z = hi_tf32(v.z); h.w = hi_tf32(v.w);
    l.x = lo_tf32(v.x, h.x); l.y = lo_tf32(v.y, h.y);
    l.z = lo_tf32(v.z, h.z); l.w = lo_tf32(v.w, h.w);
    *(uint4*)dH = h;
    *(uint4*)dL = l;
}

#define RS 36   // m-major row stride (floats): conflict-free for frag reads + f4 stores

// ---------------------------------------------------------------------------
// Kernel 1: energy[b] = q qᵀ  (3xTF32 mma.sync, symmetric: 10 blocks + mirror)
// Block 128x128, BK=32, 256 thr (8 warps, 2x4), double-buffered smem.
// ---------------------------------------------------------------------------
#define ETILE  (128 * RS)                 // 4608 u32 per tile
#define ESTAGE (4 * ETILE)                // AH|AL|BH|BL
#define ESMEM_BYTES (2 * ESTAGE * 4)      // 147456

__global__ __launch_bounds__(256) void energy_kernel(const float* __restrict__ x)
{
    extern __shared__ uint32_t sm[];
    const int tid = threadIdx.x, lane = tid & 31, wid = tid >> 5;
    const int b = blockIdx.y;

    // decode upper-triangle pair (bi <= bj) from blockIdx.x in [0,10)
    int bi = 0, t = blockIdx.x, rowlen = 4;
    while (t >= rowlen) { t -= rowlen; bi++; rowlen--; }
    const int bj = bi + t;

    const float* q = x + (size_t)b * CCH * NPIX;
    const int m0 = bi * 128, n0 = bj * 128;

    const int wm = (wid >> 2) * 64, wn = (wid & 3) * 32;
    const int qm = lane >> 2, qp = lane & 3;

    int rr[4], cc[4];
#pragma unroll
    for (int i = 0; i < 4; i++) { int idx = tid + 256 * i; rr[i] = idx >> 3; cc[i] = (idx & 7) * 4; }

    float acc[4][4][4];
#pragma unroll
    for (int i = 0; i < 4; i++)
#pragma unroll
        for (int j = 0; j < 4; j++)
#pragma unroll
            for (int k = 0; k < 4; k++) acc[i][j][k] = 0.f;

    float4 ra[4], rb[4];
    // prologue: chunk 0
#pragma unroll
    for (int i = 0; i < 4; i++) {
        ra[i] = *(const float4*)(q + (size_t)(m0 + rr[i]) * NPIX + cc[i]);
        rb[i] = *(const float4*)(q + (size_t)(n0 + rr[i]) * NPIX + cc[i]);
    }
    {
        uint32_t* S = sm;
#pragma unroll
        for (int i = 0; i < 4; i++) {
            int off = rr[i] * RS + cc[i];
            split_store(S + off,              S + ETILE + off,     ra[i]);
            split_store(S + 2 * ETILE + off,  S + 3 * ETILE + off, rb[i]);
        }
    }
    __syncthreads();

    int s = 0;
    constexpr int NCH = NPIX / 32;   // 128
    for (int it = 0; it < NCH; ++it) {
        if (it + 1 < NCH) {
            const int k0 = (it + 1) * 32;
#pragma unroll
            for (int i = 0; i < 4; i++) {
                ra[i] = *(const float4*)(q + (size_t)(m0 + rr[i]) * NPIX + k0 + cc[i]);
                rb[i] = *(const float4*)(q + (size_t)(n0 + rr[i]) * NPIX + k0 + cc[i]);
            }
        }
        // ---- compute from stage s ----
        {
            const uint32_t* AH = sm + s * ESTAGE;
            const uint32_t* AL = AH + ETILE;
            const uint32_t* BH = AH + 2 * ETILE;
            const uint32_t* BL = AH + 3 * ETILE;
#pragma unroll
            for (int kk = 0; kk < 32; kk += 8) {
                uint32_t a[4][4], bh[4][2], bl[4][2];
#pragma unroll
                for (int j = 0; j < 4; j++) {
                    const int ro = (wn + j * 8 + qm) * RS + kk + qp;
                    bh[j][0] = BH[ro]; bh[j][1] = BH[ro + 4];
                    bl[j][0] = BL[ro]; bl[j][1] = BL[ro + 4];
                }
#pragma unroll
                for (int i = 0; i < 4; i++) {
                    const int ro = (wm + i * 16 + qm) * RS + kk + qp;
                    a[i][0] = AH[ro]; a[i][1] = AH[ro + 8 * RS];
                    a[i][2] = AH[ro + 4]; a[i][3] = AH[ro + 8 * RS + 4];
                }
#pragma unroll
                for (int i = 0; i < 4; i++)
#pragma unroll
                    for (int j = 0; j < 4; j++) mma8(acc[i][j], a[i], bh[j]);
#pragma unroll
                for (int i = 0; i < 4; i++)
#pragma unroll
                    for (int j = 0; j < 4; j++) mma8(acc[i][j], a[i], bl[j]);
#pragma unroll
                for (int i = 0; i < 4; i++) {
                    const int ro = (wm + i * 16 + qm) * RS + kk + qp;
                    a[i][0] = AL[ro]; a[i][1] = AL[ro + 8 * RS];
                    a[i][2] = AL[ro + 4]; a[i][3] = AL[ro + 8 * RS + 4];
                }
#pragma unroll
                for (int i = 0; i < 4; i++)
#pragma unroll
                    for (int j = 0; j < 4; j++) mma8(acc[i][j], a[i], bh[j]);
            }
        }
        if (it + 1 < NCH) {
            __syncthreads();
            uint32_t* S = sm + (s ^ 1) * ESTAGE;
#pragma unroll
            for (int i = 0; i < 4; i++) {
                int off = rr[i] * RS + cc[i];
                split_store(S + off,             S + ETILE + off,     ra[i]);
                split_store(S + 2 * ETILE + off, S + 3 * ETILE + off, rb[i]);
            }
            __syncthreads();
            s ^= 1;
        }
    }

    // ---- epilogue: write block (+ mirror for off-diagonal) ----
    float* E = g_energy + (size_t)b * CCH * CCH;
    const bool mir = (bi != bj);
#pragma unroll
    for (int i = 0; i < 4; i++)
#pragma unroll
        for (int j = 0; j < 4; j++) {
            const int m = m0 + wm + i * 16 + qm;
            const int n = n0 + wn + j * 8 + qp * 2;
            float2 v0 = make_float2(acc[i][j][0], acc[i][j][1]);
            float2 v1 = make_float2(acc[i][j][2], acc[i][j][3]);
            *(float2*)&E[(size_t)m * CCH + n]       = v0;
            *(float2*)&E[(size_t)(m + 8) * CCH + n] = v1;
            if (mir) {
                E[(size_t)n * CCH + m]           = v0.x;
                E[(size_t)(n + 1) * CCH + m]     = v0.y;
                E[(size_t)n * CCH + m + 8]       = v1.x;
                E[(size_t)(n + 1) * CCH + m + 8] = v1.y;
            }
        }
}

// ---------------------------------------------------------------------------
// Kernel 2: in-place row softmax of exp(rowmin - e)/sum  (== softmax(max - e))
// ---------------------------------------------------------------------------
__global__ __launch_bounds__(256) void softmax_kernel()
{
    const int row  = blockIdx.x * 8 + (threadIdx.x >> 5);
    const int lane = threadIdx.x & 31;
    float* e = g_energy + (size_t)row * CCH;

    float v[16];
    float mn = 3.4e38f;
#pragma unroll
    for (int i = 0; i < 16; i++) { v[i] = e[lane + i * 32]; mn = fminf(mn, v[i]); }
#pragma unroll
    for (int o = 16; o > 0; o >>= 1)
        mn = fminf(mn, __shfl_xor_sync(0xffffffffu, mn, o));
    float s = 0.f;
#pragma unroll
    for (int i = 0; i < 16; i++) { v[i] = expf(mn - v[i]); s += v[i]; }
#pragma unroll
    for (int o = 16; o > 0; o >>= 1)
        s += __shfl_xor_sync(0xffffffffu, s, o);
    const float r = 1.0f / s;
#pragma unroll
    for (int i = 0; i < 16; i++) e[lane + i * 32] = v[i] * r;
}

// ---------------------------------------------------------------------------
// Kernel 3: y[b] = gamma * (attn[b] @ q[b]) + x[b]   (3xTF32 mma.sync)
// A = attn [C,C] m-major smem; B = q [C,N] k-major smem [32][132].
// ---------------------------------------------------------------------------
#define BRS 132
#define OTILE_A (128 * RS)                 // 4608 u32
#define OTILE_B (32 * BRS)                 // 4224 u32
#define OSTAGE  (2 * OTILE_A + 2 * OTILE_B)
#define OSMEM_BYTES (2 * OSTAGE * 4)       // 141312

__global__ __launch_bounds__(256) void out_kernel(const float* __restrict__ x,
                                                  const float* __restrict__ gamma,
                                                  float* __restrict__ out)
{
    extern __shared__ uint32_t sm[];
    const int tid = threadIdx.x, lane = tid & 31, wid = tid >> 5;
    const int b = blockIdx.z;
    const float* A = g_energy + (size_t)b * CCH * CCH;
    const float* q = x + (size_t)b * CCH * NPIX;
    const int m0 = blockIdx.y * 128;
    const int n0 = blockIdx.x * 128;

    const int wm = (wid >> 2) * 64, wn = (wid & 3) * 32;
    const int qm = lane >> 2, qp = lane & 3;

    int ar[4], ac[4], bk[4], bn[4];
#pragma unroll
    for (int i = 0; i < 4; i++) {
        int idx = tid + 256 * i;
        ar[i] = idx >> 3;  ac[i] = (idx & 7) * 4;    // A tile 128x32
        bk[i] = idx >> 5;  bn[i] = (idx & 31) * 4;   // B tile 32x128
    }

    float acc[4][4][4];
#pragma unroll
    for (int i = 0; i < 4; i++)
#pragma unroll
        for (int j = 0; j < 4; j++)
#pragma unroll
            for (int k = 0; k < 4; k++) acc[i][j][k] = 0.f;

    float4 ra[4], rb[4];
#pragma unroll
    for (int i = 0; i < 4; i++) {
        ra[i] = *(const float4*)(A + (size_t)(m0 + ar[i]) * CCH + ac[i]);
        rb[i] = *(const float4*)(q + (size_t)bk[i] * NPIX + n0 + bn[i]);
    }
    {
        uint32_t* S = sm;
#pragma unroll
        for (int i = 0; i < 4; i++) {
            int aoff = ar[i] * RS + ac[i];
            int boff = bk[i] * BRS + bn[i];
            split_store(S + aoff,               S + OTILE_A + aoff,               ra[i]);
            split_store(S + 2 * OTILE_A + boff, S + 2 * OTILE_A + OTILE_B + boff, rb[i]);
        }
    }
    __syncthreads();

    int s = 0;
    constexpr int NCH = CCH / 32;   // 16
    for (int it = 0; it < NCH; ++it) {
        if (it + 1 < NCH) {
            const int k0 = (it + 1) * 32;
#pragma unroll
            for (int i = 0; i < 4; i++) {
                ra[i] = *(const float4*)(A + (size_t)(m0 + ar[i]) * CCH + k0 + ac[i]);
                rb[i] = *(const float4*)(q + (size_t)(k0 + bk[i]) * NPIX + n0 + bn[i]);
            }
        }
        {
            const uint32_t* AH = sm + s * OSTAGE;
            const uint32_t* AL = AH + OTILE_A;
            const uint32_t* BH = AH + 2 * OTILE_A;
            const uint32_t* BL = BH + OTILE_B;
#pragma unroll
            for (int kk = 0; kk < 32; kk += 8) {
                uint32_t a[4][4], bh[4][2], bl[4][2];
#pragma unroll
                for (int j = 0; j < 4; j++) {
                    const int co = wn + j * 8 + qm;
                    bh[j][0] = BH[(kk + qp) * BRS + co];
                    bh[j][1] = BH[(kk + 4 + qp) * BRS + co];
                    bl[j][0] = BL[(kk + qp) * BRS + co];
                    bl[j][1] = BL[(kk + 4 + qp) * BRS + co];
                }
#pragma unroll
                for (int i = 0; i < 4; i++) {
                    const int ro = (wm + i * 16 + qm) * RS + kk + qp;
                    a[i][0] = AH[ro]; a[i][1] = AH[ro + 8 * RS];
                    a[i][2] = AH[ro + 4]; a[i][3] = AH[ro + 8 * RS + 4];
                }
#pragma unroll
                for (int i = 0; i < 4; i++)
#pragma unroll
                    for (int j = 0; j < 4; j++) mma8(acc[i][j], a[i], bh[j]);
#pragma unroll
                for (int i = 0; i < 4; i++)
#pragma unroll
                    for (int j = 0; j < 4; j++) mma8(acc[i][j], a[i], bl[j]);
#pragma unroll
                for (int i = 0; i < 4; i++) {
                    const int ro = (wm + i * 16 + qm) * RS + kk + qp;
                    a[i][0] = AL[ro]; a[i][1] = AL[ro + 8 * RS];
                    a[i][2] = AL[ro + 4]; a[i][3] = AL[ro + 8 * RS + 4];
                }
#pragma unroll
                for (int i = 0; i < 4; i++)
#pragma unroll
                    for (int j = 0; j < 4; j++) mma8(acc[i][j], a[i], bh[j]);
            }
        }
        if (it + 1 < NCH) {
            __syncthreads();
            uint32_t* S = sm + (s ^ 1) * OSTAGE;
#pragma unroll
            for (int i = 0; i < 4; i++) {
                int aoff = ar[i] * RS + ac[i];
                int boff = bk[i] * BRS + bn[i];
                split_store(S + aoff,               S + OTILE_A + aoff,               ra[i]);
                split_store(S + 2 * OTILE_A + boff, S + 2 * OTILE_A + OTILE_B + boff, rb[i]);
            }
            __syncthreads();
            s ^= 1;
        }
    }

    const float g = *gamma;
#pragma unroll
    for (int i = 0; i < 4; i++)
#pragma unroll
        for (int j = 0; j < 4; j++) {
            const int m = m0 + wm + i * 16 + qm;
            const int n = n0 + wn + j * 8 + qp * 2;
            {
                const size_t p = (size_t)(b * CCH + m) * NPIX + n;
                float2 xv = *(const float2*)(x + p);
                float2 o;
                o.x = fmaf(g, acc[i][j][0], xv.x);
                o.y = fmaf(g, acc[i][j][1], xv.y);
                *(float2*)(out + p) = o;
            }
            {
                const size_t p = (size_t)(b * CCH + m + 8) * NPIX + n;
                float2 xv = *(const float2*)(x + p);
                float2 o;
                o.x = fmaf(g, acc[i][j][2], xv.x);
                o.y = fmaf(g, acc[i][j][3], xv.y);
                *(float2*)(out + p) = o;
            }
        }
}

// ---------------------------------------------------------------------------
extern "C" void kernel_launch(void* const* d_in, const int* in_sizes, int n_in,
                              void* d_out, int out_size)
{
    const float* x     = (const float*)d_in[0];
    const float* gamma = (const float*)d_in[1];
    float* out = (float*)d_out;

    cudaFuncSetAttribute(energy_kernel,
                         cudaFuncAttributeMaxDynamicSharedMemorySize, ESMEM_BYTES);
    cudaFuncSetAttribute(out_kernel,
                         cudaFuncAttributeMaxDynamicSharedMemorySize, OSMEM_BYTES);

    energy_kernel<<<dim3(10, BATCH), 256, ESMEM_BYTES>>>(x);
    softmax_kernel<<<(BATCH * CCH) / 8, 256>>>();
    out_kernel<<<dim3(NPIX / 128, CCH / 128, BATCH), 256, OSMEM_BYTES>>>(x, gamma, out);
}